// round 7
// baseline (speedup 1.0000x reference)
#include <cuda_runtime.h>

#define N_NODES 100000
#define N_EDGES 1000000
#define D 64

// Scratch accumulator for scatter_add(messages) (zero-initialized each call;
// residual `+ features` is folded into the GEMM).
// float4 => 16B alignment for vector stores / red.global.add.v4.f32.
__device__ float4 g_agg4[N_NODES * (D / 4)];

// Dtype flag for edge_index: 1 = int64, 0 = int32. Set by probe_kernel.
__device__ int g_ei_is64;

// ---------------------------------------------------------------------------
// Probe: decide whether edge_index is int64 or int32 (parallel, 1 warp).
// If int64 (values < 2^31), every odd 32-bit word is 0.
// ---------------------------------------------------------------------------
__global__ void probe_kernel(const unsigned int* __restrict__ ei_words) {
    int lane = threadIdx.x;
    unsigned int nz = 0;
#pragma unroll
    for (int r = 0; r < 4; r++) {
        nz |= ei_words[2 * (lane + 32 * r) + 1];
    }
    unsigned int any = __ballot_sync(0xFFFFFFFFu, nz != 0u);
    if (lane == 0) g_ei_is64 = (any == 0u) ? 1 : 0;
}

// ---------------------------------------------------------------------------
// Kernel 1: agg = 0 (write-only; residual folded into GEMM).
// ---------------------------------------------------------------------------
__global__ void init_kernel() {
    int i = blockIdx.x * blockDim.x + threadIdx.x;
    const int total = N_NODES * (D / 4);
    if (i < total) {
        g_agg4[i] = make_float4(0.f, 0.f, 0.f, 0.f);
    }
}

// ---------------------------------------------------------------------------
// Kernel 2: edge scatter. 16 lanes per edge, one float4 per lane.
//   agg[dst][j] += feat[src][j] * w   via red.global.add.v4.f32 (sm_90+).
// ---------------------------------------------------------------------------
__global__ void scatter_kernel(const float4* __restrict__ feat4,
                               const void* __restrict__ edge_index,
                               const float* __restrict__ edge_weight) {
    int gid = blockIdx.x * blockDim.x + threadIdx.x;   // 16M lanes total
    int e = gid >> 4;       // edge id
    int j = gid & 15;       // float4 chunk within the 64-float row
    if (e >= N_EDGES) return;

    int src, dst;
    if (g_ei_is64) {
        const long long* ei = (const long long*)edge_index;
        src = (int)ei[e];
        dst = (int)ei[N_EDGES + e];
    } else {
        const int* ei = (const int*)edge_index;
        src = ei[e];
        dst = ei[N_EDGES + e];
    }
    if ((unsigned)src >= N_NODES || (unsigned)dst >= N_NODES) return;

    float w = edge_weight[e];

    float4 f = feat4[src * 16 + j];
    f.x *= w; f.y *= w; f.z *= w; f.w *= w;

    float4* p = g_agg4 + dst * 16 + j;
    asm volatile("red.global.add.v4.f32 [%0], {%1, %2, %3, %4};"
                 :: "l"(p), "f"(f.x), "f"(f.y), "f"(f.z), "f"(f.w)
                 : "memory");
}

// ---------------------------------------------------------------------------
// Kernel 3: out = (agg + feat) @ W^T + b.
// Register-tiled: 128 threads compute a 128-node x 64-out tile;
// thread (mt, nt): 8 nodes (4 f32x2 pairs along m) x 8 outputs.
//
// x tile staged TRANSPOSED in smem (xs[k][m]) in two K-halves.
// W staged k-major with each value DUPLICATED: ws2[k][2n] = ws2[k][2n+1]
//   = W[n][k], so one LDS.128 yields {wj,wj,wj+1,wj+1} -- two f32x2
//   operands with ZERO packing movs.
// Inner loop per k: 2 LDS.128 (x) + 4 LDS.128 (w) + 32 fma.rn.f32x2.
// ---------------------------------------------------------------------------
__global__ void __launch_bounds__(128) gemm_kernel(const float4* __restrict__ feat4,
                                                   const float* __restrict__ W,
                                                   const float* __restrict__ bias,
                                                   float* __restrict__ out) {
    __shared__ float xs[32][128];     // 16 KB: xs[k - half*32][m]
    __shared__ float ws2[64][128];    // 32 KB: ws2[k][2n{+0,1}] = W[n][k] dup'd

    const int tid = threadIdx.x;
    const int nt = tid >> 4;          // 0..7  -> outputs nt*8 .. nt*8+7
    const int mt = tid & 15;          // 0..15 -> nodes   mt*8 .. mt*8+7
    const int base = blockIdx.x * 128;

    // Stage W duplicated, k-major. 4096 values, 32 per thread.
    for (int idx = tid; idx < 4096; idx += 128) {
        int k = idx >> 6;
        int n = idx & 63;
        float w = W[n * 64 + k];
        *(float2*)&ws2[k][2 * n] = make_float2(w, w);
    }

    // Init accumulators with bias (replicated into both f32x2 lanes).
    unsigned long long acc[8][4];
#pragma unroll
    for (int j = 0; j < 8; j++) {
        float bj = __ldg(&bias[nt * 8 + j]);
        unsigned long long bp;
        asm("mov.b64 %0, {%1, %1};" : "=l"(bp) : "f"(bj));
#pragma unroll
        for (int i = 0; i < 4; i++) acc[j][i] = bp;
    }

    const int my_node = base + tid;
    const bool valid = my_node < N_NODES;

#pragma unroll
    for (int h = 0; h < 2; h++) {
        if (h) __syncthreads();   // protect xs before overwrite
        // Stage this K-half of x = agg + feat, transposed. Zero-fill tail.
#pragma unroll
        for (int c = 0; c < 8; c++) {
            float4 v = make_float4(0.f, 0.f, 0.f, 0.f);
            if (valid) {
                float4 a = g_agg4[my_node * 16 + h * 8 + c];
                float4 f = feat4[my_node * 16 + h * 8 + c];
                v = make_float4(a.x + f.x, a.y + f.y, a.z + f.z, a.w + f.w);
            }
            xs[c * 4 + 0][tid] = v.x;
            xs[c * 4 + 1][tid] = v.y;
            xs[c * 4 + 2][tid] = v.z;
            xs[c * 4 + 3][tid] = v.w;
        }
        __syncthreads();

#pragma unroll 8
        for (int kk = 0; kk < 32; kk++) {
            const int k = h * 32 + kk;
            // x pairs: 4 x f32x2 along the node dimension
            ulonglong2 xa = *(const ulonglong2*)&xs[kk][mt * 8];
            ulonglong2 xb = *(const ulonglong2*)&xs[kk][mt * 8 + 4];
            unsigned long long xp0 = xa.x, xp1 = xa.y, xp2 = xb.x, xp3 = xb.y;
#pragma unroll
            for (int jj = 0; jj < 4; jj++) {
                // one LDS.128 = {w, w, w', w'} for outputs 2jj, 2jj+1
                ulonglong2 wp = *(const ulonglong2*)&ws2[k][nt * 16 + 4 * jj];
                unsigned long long w0 = wp.x, w1 = wp.y;
                asm("fma.rn.f32x2 %0, %1, %2, %0;" : "+l"(acc[2*jj+0][0]) : "l"(xp0), "l"(w0));
                asm("fma.rn.f32x2 %0, %1, %2, %0;" : "+l"(acc[2*jj+0][1]) : "l"(xp1), "l"(w0));
                asm("fma.rn.f32x2 %0, %1, %2, %0;" : "+l"(acc[2*jj+0][2]) : "l"(xp2), "l"(w0));
                asm("fma.rn.f32x2 %0, %1, %2, %0;" : "+l"(acc[2*jj+0][3]) : "l"(xp3), "l"(w0));
                asm("fma.rn.f32x2 %0, %1, %2, %0;" : "+l"(acc[2*jj+1][0]) : "l"(xp0), "l"(w1));
                asm("fma.rn.f32x2 %0, %1, %2, %0;" : "+l"(acc[2*jj+1][1]) : "l"(xp1), "l"(w1));
                asm("fma.rn.f32x2 %0, %1, %2, %0;" : "+l"(acc[2*jj+1][2]) : "l"(xp2), "l"(w1));
                asm("fma.rn.f32x2 %0, %1, %2, %0;" : "+l"(acc[2*jj+1][3]) : "l"(xp3), "l"(w1));
            }
        }
    }

    // Epilogue: unpack pairs, store 8 contiguous outputs per node.
#pragma unroll
    for (int i = 0; i < 4; i++) {
        int m0 = base + mt * 8 + 2 * i;
        float o0[8], o1[8];
#pragma unroll
        for (int j = 0; j < 8; j++) {
            float2 v = *(float2*)&acc[j][i];
            o0[j] = v.x;
            o1[j] = v.y;
        }
        if (m0 < N_NODES) {
            float4* p = (float4*)(out + (size_t)m0 * D + nt * 8);
            p[0] = make_float4(o0[0], o0[1], o0[2], o0[3]);
            p[1] = make_float4(o0[4], o0[5], o0[6], o0[7]);
        }
        if (m0 + 1 < N_NODES) {
            float4* p = (float4*)(out + (size_t)(m0 + 1) * D + nt * 8);
            p[0] = make_float4(o1[0], o1[1], o1[2], o1[3]);
            p[1] = make_float4(o1[4], o1[5], o1[6], o1[7]);
        }
    }
}

// ---------------------------------------------------------------------------
extern "C" void kernel_launch(void* const* d_in, const int* in_sizes, int n_in,
                              void* d_out, int out_size) {
    // Resolve inputs by element count (robust to metadata ordering).
    const float* feat = nullptr;
    const void*  ei   = nullptr;
    const float* ew   = nullptr;
    const float* W    = nullptr;
    const float* b    = nullptr;

    for (int i = 0; i < n_in; i++) {
        switch (in_sizes[i]) {
            case 6400000: feat = (const float*)d_in[i]; break;
            case 2000000: ei   = d_in[i];               break;
            case 1000000: ew   = (const float*)d_in[i]; break;
            case 4096:    W    = (const float*)d_in[i]; break;
            case 64:      b    = (const float*)d_in[i]; break;
        }
    }

    float* out = (float*)d_out;
    (void)out_size;

    probe_kernel<<<1, 32>>>((const unsigned int*)ei);

    const int init_total = N_NODES * (D / 4);
    init_kernel<<<(init_total + 255) / 256, 256>>>();

    const int scatter_lanes = N_EDGES * 16;
    scatter_kernel<<<(scatter_lanes + 255) / 256, 256>>>((const float4*)feat, ei, ew);

    gemm_kernel<<<(N_NODES + 127) / 128, 128>>>((const float4*)feat, W, b, out);
}